// round 3
// baseline (speedup 1.0000x reference)
#include <cuda_runtime.h>
#include <cuda_bf16.h>
#include <math.h>
#include <stdint.h>

// Problem constants
#define BATCH 2048      // B*T
#define NAG   16
#define NACT  20
#define DDIM  128
#define NSAMP 32
#define EDIM  64
#define HDIM  256
#define W1N   2560      // E*2*A
#define CATN  640       // 256(h1a)+256(hf)+64(b1)+64(vh)

// ---------------- scratch (device globals) ----------------
__device__ float g_out0[BATCH * CATN];             // fused GEMM0 output
__device__ __nv_bfloat16 g_Ahi[BATCH * HDIM];      // h1a bf16 hi
__device__ __nv_bfloat16 g_Alo[BATCH * HDIM];      // h1a bf16 lo
__device__ __nv_bfloat16 g_Bhi[W1N * HDIM];        // W1b^T bf16 hi (K-major)
__device__ __nv_bfloat16 g_Blo[W1N * HDIM];        // W1b^T bf16 lo
__device__ float g_Wcat[DDIM * CATN];
__device__ float g_bcat[CATN];
__device__ float g_w1 [BATCH * W1N];
__device__ float g_wf [BATCH * EDIM];
__device__ float g_coal[BATCH * NAG * NACT];

// ===================== PTX helpers (baseline compute_103 features only) ====
__device__ __forceinline__ uint32_t smem_to_u32(const void* p) {
    uint32_t a;
    asm("{ .reg .u64 t; cvta.to.shared.u64 t, %1; cvt.u32.u64 %0, t; }" : "=r"(a) : "l"(p));
    return a;
}
#define LDMATRIX_X4(r, a) \
    asm volatile("ldmatrix.sync.aligned.m8n8.x4.shared.b16 {%0,%1,%2,%3}, [%4];" \
        : "=r"((r)[0]), "=r"((r)[1]), "=r"((r)[2]), "=r"((r)[3]) : "r"(a))
#define MMA16816(c, a, b0, b1) \
    asm volatile("mma.sync.aligned.m16n8k16.row.col.f32.bf16.bf16.f32 " \
        "{%0,%1,%2,%3},{%4,%5,%6,%7},{%8,%9},{%0,%1,%2,%3};" \
        : "+f"((c)[0]), "+f"((c)[1]), "+f"((c)[2]), "+f"((c)[3]) \
        : "r"((a)[0]), "r"((a)[1]), "r"((a)[2]), "r"((a)[3]), "r"(b0), "r"(b1))
#define CP_ASYNC16(dst, src) \
    asm volatile("cp.async.ca.shared.global [%0], [%1], 16;" :: "r"(dst), "l"(src))
#define CP_COMMIT() asm volatile("cp.async.commit_group;" ::: "memory")
#define CP_WAIT1()  asm volatile("cp.async.wait_group 1;" ::: "memory")
#define CP_WAIT0()  asm volatile("cp.async.wait_group 0;" ::: "memory")

// ===================== prep kernels =====================
__global__ void __launch_bounds__(256)
prep_wcat(const float* __restrict__ W1a, const float* __restrict__ b1a,
          const float* __restrict__ Wfa, const float* __restrict__ bfa,
          const float* __restrict__ Wb,  const float* __restrict__ bb,
          const float* __restrict__ Wv1, const float* __restrict__ bv1)
{
    int idx = blockIdx.x * 256 + threadIdx.x;
    if (idx < DDIM * CATN) {
        int d = idx / CATN, n = idx % CATN;
        float v;
        if      (n < 256) v = W1a[d * 256 + n];
        else if (n < 512) v = Wfa[d * 256 + (n - 256)];
        else if (n < 576) v = Wb [d * 64  + (n - 512)];
        else              v = Wv1[d * 64  + (n - 576)];
        g_Wcat[idx] = v;
    }
    if (idx < CATN) {
        int n = idx;
        float v;
        if      (n < 256) v = b1a[n];
        else if (n < 512) v = bfa[n - 256];
        else if (n < 576) v = bb [n - 512];
        else              v = bv1[n - 576];
        g_bcat[n] = v;
    }
}

// transpose + bf16 hi/lo split of W1b: [256 x 2560] -> [2560 x 256]
__global__ void __launch_bounds__(1024)
trans_split(const float* __restrict__ W1b)
{
    __shared__ float t[32][33];
    int n0 = blockIdx.x * 32, k0 = blockIdx.y * 32;
    int tx = threadIdx.x, ty = threadIdx.y;
    t[ty][tx] = W1b[(size_t)(k0 + ty) * W1N + n0 + tx];
    __syncthreads();
    int n = n0 + ty, k = k0 + tx;
    float v = t[tx][ty];
    __nv_bfloat16 hi = __float2bfloat16(v);
    float lof = v - __bfloat162float(hi);
    g_Bhi[(size_t)n * HDIM + k] = hi;
    g_Blo[(size_t)n * HDIM + k] = __float2bfloat16(lof);
}

// ===================== fused GEMM0: states[2048x128] @ Wcat[128x640] =====================
__global__ void __launch_bounds__(256)
gemm0_kernel(const float* __restrict__ states)
{
    __shared__ float As[16][132];
    __shared__ float Bs[16][64];
    const int tid = threadIdx.x;
    const int m0 = blockIdx.y * 128;
    const int n0 = blockIdx.x * 64;
    const int tx = tid & 15, ty = tid >> 4;

    float acc[8][4];
#pragma unroll
    for (int i = 0; i < 8; i++)
#pragma unroll
        for (int j = 0; j < 4; j++) acc[i][j] = 0.f;

    for (int k0 = 0; k0 < DDIM; k0 += 16) {
#pragma unroll
        for (int i = 0; i < 8; i++) {
            int idx = tid + i * 256;
            int m = idx >> 4, k = idx & 15;
            As[k][m] = states[(size_t)(m0 + m) * DDIM + k0 + k];
        }
#pragma unroll
        for (int i = 0; i < 4; i++) {
            int idx = tid + i * 256;
            int k = idx >> 6, n = idx & 63;
            Bs[k][n] = g_Wcat[(size_t)(k0 + k) * CATN + n0 + n];
        }
        __syncthreads();
#pragma unroll
        for (int kk = 0; kk < 16; kk++) {
            float4 a0 = *(const float4*)&As[kk][ty * 8];
            float4 a1 = *(const float4*)&As[kk][ty * 8 + 4];
            float4 bv = *(const float4*)&Bs[kk][tx * 4];
            float av[8] = {a0.x, a0.y, a0.z, a0.w, a1.x, a1.y, a1.z, a1.w};
            float bw[4] = {bv.x, bv.y, bv.z, bv.w};
#pragma unroll
            for (int i = 0; i < 8; i++)
#pragma unroll
                for (int j = 0; j < 4; j++)
                    acc[i][j] += av[i] * bw[j];
        }
        __syncthreads();
    }

    const bool do_relu = (n0 != 512);
    float bs[4];
#pragma unroll
    for (int j = 0; j < 4; j++) bs[j] = g_bcat[n0 + tx * 4 + j];

#pragma unroll
    for (int i = 0; i < 8; i++) {
        int m = m0 + ty * 8 + i;
        float4 o;
        float* po = &o.x;
#pragma unroll
        for (int j = 0; j < 4; j++) {
            float c = acc[i][j] + bs[j];
            if (do_relu) c = fmaxf(c, 0.f);
            po[j] = c;
        }
        *(float4*)&g_out0[(size_t)m * CATN + n0 + tx * 4] = o;
        if (n0 < 256) {
            __nv_bfloat16 h[4]; float lo[4];
#pragma unroll
            for (int j = 0; j < 4; j++) {
                h[j] = __float2bfloat16(po[j]);
                lo[j] = po[j] - __bfloat162float(h[j]);
            }
            size_t base = (size_t)m * HDIM + n0 + tx * 4;
            *(__nv_bfloat162*)&g_Ahi[base]     = __nv_bfloat162(h[0], h[1]);
            *(__nv_bfloat162*)&g_Ahi[base + 2] = __nv_bfloat162(h[2], h[3]);
            *(__nv_bfloat162*)&g_Alo[base]     = __nv_bfloat162(__float2bfloat16(lo[0]), __float2bfloat16(lo[1]));
            *(__nv_bfloat162*)&g_Alo[base + 2] = __nv_bfloat162(__float2bfloat16(lo[2]), __float2bfloat16(lo[3]));
        }
    }
}

// ===================== wf GEMM: |hf @ Wfb + bfb|, 2048x64, K=256, tile 32x64 =====================
__global__ void __launch_bounds__(256)
wf_kernel(const float* __restrict__ Wfb, const float* __restrict__ bfb)
{
    __shared__ float As[16][36];
    __shared__ float Bs[16][64];
    const int tid = threadIdx.x;
    const int m0 = blockIdx.x * 32;
    const int tx = tid & 15, ty = tid >> 4;

    float acc[2][4] = {};
    for (int k0 = 0; k0 < HDIM; k0 += 16) {
        {
            int idx = tid;
            int m = idx >> 4, k = idx & 15;
            As[k][m] = g_out0[(size_t)(m0 + m) * CATN + 256 + k0 + k];
            idx = tid + 256;
            m = idx >> 4; k = idx & 15;
            As[k][m] = g_out0[(size_t)(m0 + m) * CATN + 256 + k0 + k];
        }
#pragma unroll
        for (int i = 0; i < 4; i++) {
            int idx = tid + i * 256;
            int k = idx >> 6, n = idx & 63;
            Bs[k][n] = Wfb[(size_t)(k0 + k) * EDIM + n];
        }
        __syncthreads();
#pragma unroll
        for (int kk = 0; kk < 16; kk++) {
            float a0 = As[kk][ty * 2], a1 = As[kk][ty * 2 + 1];
            float4 bv = *(const float4*)&Bs[kk][tx * 4];
            float bw[4] = {bv.x, bv.y, bv.z, bv.w};
#pragma unroll
            for (int j = 0; j < 4; j++) { acc[0][j] += a0 * bw[j]; acc[1][j] += a1 * bw[j]; }
        }
        __syncthreads();
    }
    float bs[4];
#pragma unroll
    for (int j = 0; j < 4; j++) bs[j] = bfb[tx * 4 + j];
#pragma unroll
    for (int r = 0; r < 2; r++) {
        int m = m0 + ty * 2 + r;
        float4 o;
        o.x = fabsf(acc[r][0] + bs[0]);
        o.y = fabsf(acc[r][1] + bs[1]);
        o.z = fabsf(acc[r][2] + bs[2]);
        o.w = fabsf(acc[r][3] + bs[3]);
        *(float4*)&g_wf[(size_t)m * EDIM + tx * 4] = o;
    }
}

// ===================== HMMA GEMM: w1 = |A @ B^T + b1b|  (mma.sync bf16 3-product) =====
// A: [2048 x 256] bf16 hi/lo; B: [2560 x 256] bf16 hi/lo (K-major rows)
// CTA tile 128x128, 8 warps 2x4 (warp tile 64x32), BK=32, cp.async double buffer.
// smem per tile: 128 rows x 80B (64B data + 16B pad -> conflict-free ldmatrix)
#define T_ROWB   80
#define T_BYTES  (128 * T_ROWB)      // 10240
#define STAGE_B  (4 * T_BYTES)       // 40960
#define SMEM_HMMA (2 * STAGE_B)      // 81920

__global__ void __launch_bounds__(256)
hmma_gemm(const float* __restrict__ b1b)
{
    extern __shared__ char sm[];
    const int tid = threadIdx.x;
    const int wid = tid >> 5, lane = tid & 31;
    const int n0 = blockIdx.x * 128;
    const int m0 = blockIdx.y * 128;
    const int wm = (wid >> 2) * 64;    // warp row offset in CTA tile
    const int wn = (wid & 3) * 32;     // warp col offset

    float acc[4][4][4];
#pragma unroll
    for (int r = 0; r < 4; r++)
#pragma unroll
        for (int g = 0; g < 4; g++)
#pragma unroll
            for (int c = 0; c < 4; c++) acc[r][g][c] = 0.f;

    const __nv_bfloat16* srcs[4] = {g_Ahi, g_Alo, g_Bhi, g_Blo};

    // ---- stage loader: 4 tiles x 512 16B chunks, 8 cp.async per thread ----
    auto load_stage = [&](int s, int k0) {
#pragma unroll
        for (int t = 0; t < 4; t++) {
            const int r0 = (t < 2) ? m0 : n0;
            const __nv_bfloat16* src = srcs[t];
            char* dstb = sm + s * STAGE_B + t * T_BYTES;
#pragma unroll
            for (int j = 0; j < 2; j++) {
                int idx = tid + j * 256;
                int row = idx >> 2, c = idx & 3;
                uint32_t dst = smem_to_u32(dstb + row * T_ROWB + c * 16);
                const char* sp = (const char*)(src + (size_t)(r0 + row) * HDIM + k0) + c * 16;
                CP_ASYNC16(dst, sp);
            }
        }
    };

    load_stage(0, 0);
    CP_COMMIT();

    for (int kc = 0; kc < 8; kc++) {
        if (kc < 7) { load_stage((kc + 1) & 1, (kc + 1) * 32); CP_COMMIT(); CP_WAIT1(); }
        else        { CP_WAIT0(); }
        __syncthreads();

        char* Ah = sm + (kc & 1) * STAGE_B;
        char* Al = Ah + T_BYTES;
        char* Bh = Ah + 2 * T_BYTES;
        char* Bl = Ah + 3 * T_BYTES;

#pragma unroll
        for (int ks = 0; ks < 2; ks++) {
            const int kb = ks * 32;      // byte offset of this k16 within 64B row data
            uint32_t ah[4][4], al[4][4], bh[2][4], bl[2][4];
            const int arow = wm + (lane & 15);
            const int akb  = kb + (lane >> 4) * 16;
#pragma unroll
            for (int r = 0; r < 4; r++) {
                LDMATRIX_X4(ah[r], smem_to_u32(Ah + (arow + r * 16) * T_ROWB + akb));
                LDMATRIX_X4(al[r], smem_to_u32(Al + (arow + r * 16) * T_ROWB + akb));
            }
            const int brow = wn + (lane & 7) + (lane >> 4) * 8;
            const int bkb  = kb + ((lane >> 3) & 1) * 16;
#pragma unroll
            for (int g = 0; g < 2; g++) {
                LDMATRIX_X4(bh[g], smem_to_u32(Bh + (brow + g * 16) * T_ROWB + bkb));
                LDMATRIX_X4(bl[g], smem_to_u32(Bl + (brow + g * 16) * T_ROWB + bkb));
            }
#pragma unroll
            for (int r = 0; r < 4; r++)
#pragma unroll
                for (int g = 0; g < 4; g++) {
                    uint32_t b0h = bh[g >> 1][(g & 1) * 2], b1h = bh[g >> 1][(g & 1) * 2 + 1];
                    uint32_t b0l = bl[g >> 1][(g & 1) * 2], b1l = bl[g >> 1][(g & 1) * 2 + 1];
                    MMA16816(acc[r][g], ah[r], b0h, b1h);   // hi*hi
                    MMA16816(acc[r][g], ah[r], b0l, b1l);   // hi*lo
                    MMA16816(acc[r][g], al[r], b0h, b1h);   // lo*hi
                }
        }
        __syncthreads();
    }

    // ---- epilogue: bias + abs ----
    const int mrow  = m0 + wm + (lane >> 2);
    const int ncol0 = n0 + wn + (lane & 3) * 2;
#pragma unroll
    for (int g = 0; g < 4; g++) {
        const int n = ncol0 + g * 8;
        float2 bias = *(const float2*)&b1b[n];
#pragma unroll
        for (int r = 0; r < 4; r++) {
            const int m = mrow + r * 16;
            float2 o0, o1;
            o0.x = fabsf(acc[r][g][0] + bias.x);
            o0.y = fabsf(acc[r][g][1] + bias.y);
            o1.x = fabsf(acc[r][g][2] + bias.x);
            o1.y = fabsf(acc[r][g][3] + bias.y);
            *(float2*)&g_w1[(size_t)m * W1N + n]       = o0;
            *(float2*)&g_w1[(size_t)(m + 8) * W1N + n] = o1;
        }
    }
}

// ===================== coalition kernel =====================
__global__ void __launch_bounds__(320)
coal_kernel(const float* __restrict__ actions, const int* __restrict__ gc)
{
    int b = blockIdx.x;
    int tid = threadIdx.x;
    int i = tid / NACT, a = tid % NACT;

    __shared__ float act_s[NAG][NACT];
    __shared__ int   gcs[NSAMP][NAG];
    __shared__ float S[NAG][NACT];
    __shared__ float Q[NAG][NACT];

    act_s[i][a] = actions[b * NAG * NACT + tid];
    for (int idx = tid; idx < NSAMP * NAG; idx += 320)
        ((int*)gcs)[idx] = gc[b * NSAMP * NAG + idx];
    __syncthreads();

    float acc = 0.f;
    for (int s = 0; s < NSAMP; s++) {
        S[i][a] = act_s[gcs[s][i]][a];
        __syncthreads();
        float q = 0.f;
        for (int j = 0; j < i; j++) q += S[j][a];
        Q[i][a] = q;
        __syncthreads();
        int g = gcs[s][i];
        acc += (float)g * Q[g][a];
        __syncthreads();
    }
    g_coal[b * NAG * NACT + i * NACT + a] = acc * (1.f / (16.f * 32.f));
}

// ===================== final mix (v fused) =====================
__global__ void __launch_bounds__(1024)
final_kernel(const float* __restrict__ actions, const float* __restrict__ Wv2,
             const float* __restrict__ bv2, const float* __restrict__ agent_qs,
             float* __restrict__ q_out, float* __restrict__ w_out)
{
    int b = blockIdx.x;
    int tid = threadIdx.x;
    int i = tid >> 6, e = tid & 63;

    __shared__ float w1s[W1N];
    __shared__ float ins[NAG][40];
    __shared__ float wfs[EDIM], b1s[EDIM];
    __shared__ float red[32], vred[2];
    __shared__ float qpart[NAG];

    for (int idx = tid; idx < W1N; idx += 1024)
        w1s[idx] = g_w1[(size_t)b * W1N + idx];
    if (tid < 320)
        ins[tid / NACT][tid % NACT] = g_coal[b * NAG * NACT + tid];
    else if (tid < 640) {
        int t = tid - 320;
        ins[t / NACT][NACT + t % NACT] = actions[b * NAG * NACT + t];
    } else if (tid < 704) {
        int ee = tid - 640;
        float pv = g_out0[(size_t)b * CATN + 576 + ee] * Wv2[ee];
#pragma unroll
        for (int o = 16; o > 0; o >>= 1)
            pv += __shfl_down_sync(0xffffffffu, pv, o);
        if ((ee & 31) == 0) vred[ee >> 5] = pv;
    } else if (tid < 768) {
        wfs[tid - 704] = g_wf[(size_t)b * EDIM + tid - 704];
    } else if (tid < 832) {
        b1s[tid - 768] = g_out0[(size_t)b * CATN + 512 + (tid - 768)];
    }
    __syncthreads();

    float h = b1s[e];
#pragma unroll
    for (int k = 0; k < 40; k++)
        h += ins[i][k] * w1s[k * EDIM + e];
    float hid = h > 0.f ? h : expm1f(h);
    float pr = hid * wfs[e];
#pragma unroll
    for (int o = 16; o > 0; o >>= 1)
        pr += __shfl_down_sync(0xffffffffu, pr, o);
    if ((tid & 31) == 0) red[tid >> 5] = pr;
    __syncthreads();
    if (e == 0) {
        float y = red[i * 2] + red[i * 2 + 1] + (vred[0] + vred[1] + bv2[0]);
        float w = fabsf(y);
        if (w_out) w_out[b * NAG + i] = w;
        qpart[i] = w * agent_qs[b * NAG + i];
    }
    __syncthreads();
    if (tid == 0 && q_out) {
        float q = 0.f;
#pragma unroll
        for (int ii = 0; ii < NAG; ii++) q += qpart[ii];
        q_out[b] = q;
    }
}

// ===================== launch =====================
extern "C" void kernel_launch(void* const* d_in, const int* in_sizes, int n_in,
                              void* d_out, int out_size)
{
    const float* states    = (const float*)d_in[0];
    const float* actions   = (const float*)d_in[1];
    const float* agent_qs  = (const float*)d_in[2];
    const int*   gc        = (const int*)  d_in[4];
    const float* W1a = (const float*)d_in[5];
    const float* b1a = (const float*)d_in[6];
    const float* W1b = (const float*)d_in[7];
    const float* b1b = (const float*)d_in[8];
    const float* Wb  = (const float*)d_in[9];
    const float* bb  = (const float*)d_in[10];
    const float* Wfa = (const float*)d_in[11];
    const float* bfa = (const float*)d_in[12];
    const float* Wfb = (const float*)d_in[13];
    const float* bfb = (const float*)d_in[14];
    const float* Wv1 = (const float*)d_in[15];
    const float* bv1 = (const float*)d_in[16];
    const float* Wv2 = (const float*)d_in[17];
    const float* bv2 = (const float*)d_in[18];

    static bool inited = false;
    if (!inited) {
        cudaFuncSetAttribute(hmma_gemm, cudaFuncAttributeMaxDynamicSharedMemorySize, SMEM_HMMA);
        inited = true;
    }

    float* out = (float*)d_out;
    float* q_out = nullptr;
    float* w_out = nullptr;
    if (out_size == BATCH + BATCH * NAG)      { q_out = out; w_out = out + BATCH; }
    else if (out_size == BATCH * NAG)         { w_out = out; }
    else if (out_size == BATCH)               { q_out = out; }
    else                                      { q_out = out; w_out = out + BATCH; }

    // prep: concat weights + transpose/split W1b
    prep_wcat<<<(DDIM * CATN + 255) / 256, 256>>>(W1a, b1a, Wfa, bfa, Wb, bb, Wv1, bv1);
    trans_split<<<dim3(W1N / 32, HDIM / 32), dim3(32, 32)>>>(W1b);
    // fused states GEMM -> h1a(bf16 hi/lo) | hf | b1 | vh
    gemm0_kernel<<<dim3(CATN / 64, BATCH / 128), 256>>>(states);
    // wf = |hf @ Wfb + bfb|
    wf_kernel<<<BATCH / 32, 256>>>(Wfb, bfb);
    // dominant GEMM on HMMA tensor path (bf16 3-product split)
    hmma_gemm<<<dim3(W1N / 128, BATCH / 128), 256, SMEM_HMMA>>>(b1b);
    // coalition inputs
    coal_kernel<<<BATCH, 320>>>(actions, gc);
    // final fused mix (+v)
    final_kernel<<<BATCH, 1024>>>(actions, Wv2, bv2, agent_qs, q_out, w_out);
}

// round 4
// speedup vs baseline: 2.3055x; 2.3055x over previous
#include <cuda_runtime.h>
#include <cuda_bf16.h>
#include <math.h>
#include <stdint.h>

// Problem constants
#define BATCH 2048      // B*T
#define NAG   16
#define NACT  20
#define DDIM  128
#define NSAMP 32
#define EDIM  64
#define HDIM  256
#define W1N   2560      // E*2*A
#define CATN  640       // 256(h1a)+256(hf)+64(b1)+64(vh)

// ---------------- scratch (device globals) ----------------
__device__ float g_out0[BATCH * CATN];
__device__ __nv_bfloat16 g_Ahi[BATCH * HDIM];
__device__ __nv_bfloat16 g_Alo[BATCH * HDIM];
__device__ __nv_bfloat16 g_Bhi[W1N * HDIM];
__device__ __nv_bfloat16 g_Blo[W1N * HDIM];
__device__ float g_w1 [BATCH * W1N];
__device__ float g_wf [BATCH * EDIM];
__device__ float g_coal[BATCH * NAG * NACT];

// ===================== PTX helpers =====================
__device__ __forceinline__ uint32_t smem_to_u32(const void* p) {
    uint32_t a;
    asm("{ .reg .u64 t; cvta.to.shared.u64 t, %1; cvt.u32.u64 %0, t; }" : "=r"(a) : "l"(p));
    return a;
}
#define LDMATRIX_X4(r, a) \
    asm volatile("ldmatrix.sync.aligned.m8n8.x4.shared.b16 {%0,%1,%2,%3}, [%4];" \
        : "=r"((r)[0]), "=r"((r)[1]), "=r"((r)[2]), "=r"((r)[3]) : "r"(a))
#define MMA16816(c, a, b0, b1) \
    asm volatile("mma.sync.aligned.m16n8k16.row.col.f32.bf16.bf16.f32 " \
        "{%0,%1,%2,%3},{%4,%5,%6,%7},{%8,%9},{%0,%1,%2,%3};" \
        : "+f"((c)[0]), "+f"((c)[1]), "+f"((c)[2]), "+f"((c)[3]) \
        : "r"((a)[0]), "r"((a)[1]), "r"((a)[2]), "r"((a)[3]), "r"(b0), "r"(b1))
#define CP_ASYNC16(dst, src) \
    asm volatile("cp.async.ca.shared.global [%0], [%1], 16;" :: "r"(dst), "l"(src))
#define CP_COMMIT() asm volatile("cp.async.commit_group;" ::: "memory")
#define CP_WAIT1()  asm volatile("cp.async.wait_group 1;" ::: "memory")
#define CP_WAIT0()  asm volatile("cp.async.wait_group 0;" ::: "memory")

// ===================== trans_split: W1b [256x2560] -> bf16 hi/lo [2560x256] =====
__global__ void __launch_bounds__(256)
trans_split(const float* __restrict__ W1b)
{
    __shared__ float t[32][33];
    int n0 = blockIdx.x * 32, k0 = blockIdx.y * 32;
    int tx = threadIdx.x & 31, ty = threadIdx.x >> 5;   // 32 x 8
#pragma unroll
    for (int r = 0; r < 4; r++)
        t[ty * 4 + r][tx] = W1b[(size_t)(k0 + ty * 4 + r) * W1N + n0 + tx];
    __syncthreads();
#pragma unroll
    for (int r = 0; r < 4; r++) {
        int n = n0 + ty * 4 + r, k = k0 + tx;
        float v = t[tx][ty * 4 + r];
        __nv_bfloat16 hi = __float2bfloat16(v);
        float lof = v - __bfloat162float(hi);
        g_Bhi[(size_t)n * HDIM + k] = hi;
        g_Blo[(size_t)n * HDIM + k] = __float2bfloat16(lof);
    }
}

// ===================== gemm0: states[2048x128] @ [W1a|Wfa|Wb|Wv1] =====================
// 64x64 tile, 256 threads, 4x4 microtile, K=128 in 4 chunks of 32, cp.async x2 buffer.
__global__ void __launch_bounds__(256)
gemm0_kernel(const float* __restrict__ states,
             const float* __restrict__ W1a, const float* __restrict__ b1a,
             const float* __restrict__ Wfa, const float* __restrict__ bfa,
             const float* __restrict__ Wb,  const float* __restrict__ bb,
             const float* __restrict__ Wv1, const float* __restrict__ bv1)
{
    __shared__ float As[2][64][36];
    __shared__ float Bs[2][32][64];

    const int tid = threadIdx.x;
    const int m0 = blockIdx.y * 64;
    const int n0 = blockIdx.x * 64;
    const int tx = tid & 15, ty = tid >> 4;

    const float* Bsrc; const float* bias; int ldb; int nc0;
    if      (n0 < 256) { Bsrc = W1a; bias = b1a; ldb = 256; nc0 = n0; }
    else if (n0 < 512) { Bsrc = Wfa; bias = bfa; ldb = 256; nc0 = n0 - 256; }
    else if (n0 < 576) { Bsrc = Wb;  bias = bb;  ldb = 64;  nc0 = 0; }
    else               { Bsrc = Wv1; bias = bv1; ldb = 64;  nc0 = 0; }

    auto load_stage = [&](int s, int k0) {
        // A: 64 rows x 32 floats = 512 chunks of 16B
#pragma unroll
        for (int j = 0; j < 2; j++) {
            int idx = tid * 2 + j;
            int row = idx >> 3, c = idx & 7;
            CP_ASYNC16(smem_to_u32(&As[s][row][c * 4]),
                       states + (size_t)(m0 + row) * DDIM + k0 + c * 4);
        }
        // B: 32 rows x 64 floats = 512 chunks
#pragma unroll
        for (int j = 0; j < 2; j++) {
            int idx = tid * 2 + j;
            int k = idx >> 4, c = idx & 15;
            CP_ASYNC16(smem_to_u32(&Bs[s][k][c * 4]),
                       Bsrc + (size_t)(k0 + k) * ldb + nc0 + c * 4);
        }
    };

    float acc[4][4];
#pragma unroll
    for (int r = 0; r < 4; r++)
#pragma unroll
        for (int j = 0; j < 4; j++) acc[r][j] = 0.f;

    load_stage(0, 0);
    CP_COMMIT();

    for (int c = 0; c < 4; c++) {
        if (c < 3) { load_stage((c + 1) & 1, (c + 1) * 32); CP_COMMIT(); CP_WAIT1(); }
        else       { CP_WAIT0(); }
        __syncthreads();
        const int buf = c & 1;
#pragma unroll
        for (int kk = 0; kk < 32; kk++) {
            float av[4];
#pragma unroll
            for (int r = 0; r < 4; r++) av[r] = As[buf][ty * 4 + r][kk];
            float4 bv = *(const float4*)&Bs[buf][kk][tx * 4];
            float bw[4] = {bv.x, bv.y, bv.z, bv.w};
#pragma unroll
            for (int r = 0; r < 4; r++)
#pragma unroll
                for (int j = 0; j < 4; j++)
                    acc[r][j] += av[r] * bw[j];
        }
        __syncthreads();
    }

    const bool do_relu = (n0 != 512);
    float bs[4];
#pragma unroll
    for (int j = 0; j < 4; j++) bs[j] = bias[nc0 + tx * 4 + j];

#pragma unroll
    for (int r = 0; r < 4; r++) {
        int m = m0 + ty * 4 + r;
        float4 o;
        float* po = &o.x;
#pragma unroll
        for (int j = 0; j < 4; j++) {
            float v = acc[r][j] + bs[j];
            if (do_relu) v = fmaxf(v, 0.f);
            po[j] = v;
        }
        *(float4*)&g_out0[(size_t)m * CATN + n0 + tx * 4] = o;
        if (n0 < 256) {
            __nv_bfloat16 h[4]; float lo[4];
#pragma unroll
            for (int j = 0; j < 4; j++) {
                h[j] = __float2bfloat16(po[j]);
                lo[j] = po[j] - __bfloat162float(h[j]);
            }
            size_t base = (size_t)m * HDIM + n0 + tx * 4;
            *(__nv_bfloat162*)&g_Ahi[base]     = __nv_bfloat162(h[0], h[1]);
            *(__nv_bfloat162*)&g_Ahi[base + 2] = __nv_bfloat162(h[2], h[3]);
            *(__nv_bfloat162*)&g_Alo[base]     = __nv_bfloat162(__float2bfloat16(lo[0]), __float2bfloat16(lo[1]));
            *(__nv_bfloat162*)&g_Alo[base + 2] = __nv_bfloat162(__float2bfloat16(lo[2]), __float2bfloat16(lo[3]));
        }
    }
}

// ===================== wf: |hf @ Wfb + bfb|  16x64 tile, grid 128 =====================
__global__ void __launch_bounds__(256)
wf_kernel(const float* __restrict__ Wfb, const float* __restrict__ bfb)
{
    __shared__ float As[2][16][36];
    __shared__ float Bs[2][32][64];
    const int tid = threadIdx.x;
    const int m0 = blockIdx.x * 16;
    const int tx = tid & 15, ty = tid >> 4;   // ty = row (16), tx*4 = cols

    auto load_stage = [&](int s, int k0) {
        if (tid < 128) {        // A: 16 rows x 32 floats = 128 chunks
            int row = tid >> 3, c = tid & 7;
            CP_ASYNC16(smem_to_u32(&As[s][row][c * 4]),
                       g_out0 + (size_t)(m0 + row) * CATN + 256 + k0 + c * 4);
        }
#pragma unroll
        for (int j = 0; j < 2; j++) {   // B: 32 rows x 64 = 512 chunks
            int idx = tid * 2 + j;
            int k = idx >> 4, c = idx & 15;
            CP_ASYNC16(smem_to_u32(&Bs[s][k][c * 4]),
                       Wfb + (size_t)(k0 + k) * EDIM + c * 4);
        }
    };

    float acc[4] = {0.f, 0.f, 0.f, 0.f};
    load_stage(0, 0);
    CP_COMMIT();

    for (int c = 0; c < 8; c++) {       // K = 256 / 32
        if (c < 7) { load_stage((c + 1) & 1, (c + 1) * 32); CP_COMMIT(); CP_WAIT1(); }
        else       { CP_WAIT0(); }
        __syncthreads();
        const int buf = c & 1;
#pragma unroll
        for (int kk = 0; kk < 32; kk++) {
            float a = As[buf][ty][kk];
            float4 bv = *(const float4*)&Bs[buf][kk][tx * 4];
            acc[0] += a * bv.x; acc[1] += a * bv.y;
            acc[2] += a * bv.z; acc[3] += a * bv.w;
        }
        __syncthreads();
    }

    float4 bsv = *(const float4*)&bfb[tx * 4];
    float4 o;
    o.x = fabsf(acc[0] + bsv.x);
    o.y = fabsf(acc[1] + bsv.y);
    o.z = fabsf(acc[2] + bsv.z);
    o.w = fabsf(acc[3] + bsv.w);
    *(float4*)&g_wf[(size_t)(m0 + ty) * EDIM + tx * 4] = o;
}

// ===================== HMMA GEMM (unchanged, working) =====================
#define T_ROWB   80
#define T_BYTES  (128 * T_ROWB)
#define STAGE_B  (4 * T_BYTES)
#define SMEM_HMMA (2 * STAGE_B)

__global__ void __launch_bounds__(256)
hmma_gemm(const float* __restrict__ b1b)
{
    extern __shared__ char sm[];
    const int tid = threadIdx.x;
    const int wid = tid >> 5, lane = tid & 31;
    const int n0 = blockIdx.x * 128;
    const int m0 = blockIdx.y * 128;
    const int wm = (wid >> 2) * 64;
    const int wn = (wid & 3) * 32;

    float acc[4][4][4];
#pragma unroll
    for (int r = 0; r < 4; r++)
#pragma unroll
        for (int g = 0; g < 4; g++)
#pragma unroll
            for (int c = 0; c < 4; c++) acc[r][g][c] = 0.f;

    const __nv_bfloat16* srcs[4] = {g_Ahi, g_Alo, g_Bhi, g_Blo};

    auto load_stage = [&](int s, int k0) {
#pragma unroll
        for (int t = 0; t < 4; t++) {
            const int r0 = (t < 2) ? m0 : n0;
            const __nv_bfloat16* src = srcs[t];
            char* dstb = sm + s * STAGE_B + t * T_BYTES;
#pragma unroll
            for (int j = 0; j < 2; j++) {
                int idx = tid + j * 256;
                int row = idx >> 2, c = idx & 3;
                CP_ASYNC16(smem_to_u32(dstb + row * T_ROWB + c * 16),
                           (const char*)(src + (size_t)(r0 + row) * HDIM + k0) + c * 16);
            }
        }
    };

    load_stage(0, 0);
    CP_COMMIT();

    for (int kc = 0; kc < 8; kc++) {
        if (kc < 7) { load_stage((kc + 1) & 1, (kc + 1) * 32); CP_COMMIT(); CP_WAIT1(); }
        else        { CP_WAIT0(); }
        __syncthreads();

        char* Ah = sm + (kc & 1) * STAGE_B;
        char* Al = Ah + T_BYTES;
        char* Bh = Ah + 2 * T_BYTES;
        char* Bl = Ah + 3 * T_BYTES;

#pragma unroll
        for (int ks = 0; ks < 2; ks++) {
            const int kb = ks * 32;
            uint32_t ah[4][4], al[4][4], bh[2][4], bl[2][4];
            const int arow = wm + (lane & 15);
            const int akb  = kb + (lane >> 4) * 16;
#pragma unroll
            for (int r = 0; r < 4; r++) {
                LDMATRIX_X4(ah[r], smem_to_u32(Ah + (arow + r * 16) * T_ROWB + akb));
                LDMATRIX_X4(al[r], smem_to_u32(Al + (arow + r * 16) * T_ROWB + akb));
            }
            const int brow = wn + (lane & 7) + (lane >> 4) * 8;
            const int bkb  = kb + ((lane >> 3) & 1) * 16;
#pragma unroll
            for (int g = 0; g < 2; g++) {
                LDMATRIX_X4(bh[g], smem_to_u32(Bh + (brow + g * 16) * T_ROWB + bkb));
                LDMATRIX_X4(bl[g], smem_to_u32(Bl + (brow + g * 16) * T_ROWB + bkb));
            }
#pragma unroll
            for (int r = 0; r < 4; r++)
#pragma unroll
                for (int g = 0; g < 4; g++) {
                    uint32_t b0h = bh[g >> 1][(g & 1) * 2], b1h = bh[g >> 1][(g & 1) * 2 + 1];
                    uint32_t b0l = bl[g >> 1][(g & 1) * 2], b1l = bl[g >> 1][(g & 1) * 2 + 1];
                    MMA16816(acc[r][g], ah[r], b0h, b1h);
                    MMA16816(acc[r][g], ah[r], b0l, b1l);
                    MMA16816(acc[r][g], al[r], b0h, b1h);
                }
        }
        __syncthreads();
    }

    const int mrow  = m0 + wm + (lane >> 2);
    const int ncol0 = n0 + wn + (lane & 3) * 2;
#pragma unroll
    for (int g = 0; g < 4; g++) {
        const int n = ncol0 + g * 8;
        float2 bias = *(const float2*)&b1b[n];
#pragma unroll
        for (int r = 0; r < 4; r++) {
            const int m = mrow + r * 16;
            float2 o0, o1;
            o0.x = fabsf(acc[r][g][0] + bias.x);
            o0.y = fabsf(acc[r][g][1] + bias.y);
            o1.x = fabsf(acc[r][g][2] + bias.x);
            o1.y = fabsf(acc[r][g][3] + bias.y);
            *(float2*)&g_w1[(size_t)m * W1N + n]       = o0;
            *(float2*)&g_w1[(size_t)(m + 8) * W1N + n] = o1;
        }
    }
}

// ===================== coalition: sync-free per-warp samples =====================
// coal[b,i,a] = (1/512) * sum_s gc[b,s,i] * Q_s[gc[b,s,i]][a],
// Q_s[m][a] = sum_{j<m} act[gc[b,s,j]][a]
__global__ void __launch_bounds__(256)
coal_kernel(const float* __restrict__ actions, const int* __restrict__ gc)
{
    const int b = blockIdx.x;
    const int tid = threadIdx.x;
    const int w = tid >> 5, a = tid & 31;

    __shared__ float act_s[NAG * NACT];      // 320
    __shared__ int   gcs[NSAMP * NAG];       // 512
    __shared__ float sbuf[8][NAG * NACT];    // per-warp Q, then partial acc

    for (int idx = tid; idx < NAG * NACT; idx += 256)
        act_s[idx] = actions[b * NAG * NACT + idx];
    for (int idx = tid; idx < NSAMP * NAG; idx += 256)
        gcs[idx] = gc[b * NSAMP * NAG + idx];
    __syncthreads();

    float accp[NAG];
#pragma unroll
    for (int i = 0; i < NAG; i++) accp[i] = 0.f;

    // each warp: 4 samples; lane a (<20) owns column a exclusively -> no syncs
#pragma unroll
    for (int si = 0; si < 4; si++) {
        const int s = w * 4 + si;
        float q = 0.f;
#pragma unroll
        for (int m = 0; m < NAG; m++) {
            int g = gcs[s * NAG + m];
            if (a < NACT) {
                sbuf[w][m * NACT + a] = q;
                q += act_s[g * NACT + a];
            }
        }
#pragma unroll
        for (int i = 0; i < NAG; i++) {
            int g = gcs[s * NAG + i];
            if (a < NACT) accp[i] += (float)g * sbuf[w][g * NACT + a];
        }
    }
    if (a < NACT) {
#pragma unroll
        for (int i = 0; i < NAG; i++) sbuf[w][i * NACT + a] = accp[i];
    }
    __syncthreads();
    for (int idx = tid; idx < NAG * NACT; idx += 256) {
        float s = 0.f;
#pragma unroll
        for (int w8 = 0; w8 < 8; w8++) s += sbuf[w8][idx];
        g_coal[b * NAG * NACT + idx] = s * (1.f / 512.f);
    }
}

// ===================== final mix (v fused) =====================
__global__ void __launch_bounds__(1024)
final_kernel(const float* __restrict__ actions, const float* __restrict__ Wv2,
             const float* __restrict__ bv2, const float* __restrict__ agent_qs,
             float* __restrict__ q_out, float* __restrict__ w_out)
{
    int b = blockIdx.x;
    int tid = threadIdx.x;
    int i = tid >> 6, e = tid & 63;

    __shared__ float w1s[W1N];
    __shared__ float ins[NAG][40];
    __shared__ float wfs[EDIM], b1s[EDIM];
    __shared__ float red[32], vred[2];
    __shared__ float qpart[NAG];

    if (tid < 640)
        ((float4*)w1s)[tid] = ((const float4*)(g_w1 + (size_t)b * W1N))[tid];
    if (tid < 320)
        ins[tid / NACT][tid % NACT] = g_coal[b * NAG * NACT + tid];
    else if (tid < 704) {
        if (tid < 640) {
            int t = tid - 320;
            ins[t / NACT][NACT + t % NACT] = actions[b * NAG * NACT + t];
        } else {
            int ee = tid - 640;
            float pv = g_out0[(size_t)b * CATN + 576 + ee] * Wv2[ee];
#pragma unroll
            for (int o = 16; o > 0; o >>= 1)
                pv += __shfl_down_sync(0xffffffffu, pv, o);
            if ((ee & 31) == 0) vred[ee >> 5] = pv;
        }
    } else if (tid < 768) {
        wfs[tid - 704] = g_wf[(size_t)b * EDIM + tid - 704];
    } else if (tid < 832) {
        b1s[tid - 768] = g_out0[(size_t)b * CATN + 512 + (tid - 768)];
    }
    // threads 320..639 also need their ins-load even though they did w1 load:
    __syncthreads();
    if (tid >= 320 && tid < 640) { /* already handled above */ }

    float h = b1s[e];
#pragma unroll
    for (int k = 0; k < 40; k++)
        h += ins[i][k] * w1s[k * EDIM + e];
    float hid = h > 0.f ? h : expm1f(h);
    float pr = hid * wfs[e];
#pragma unroll
    for (int o = 16; o > 0; o >>= 1)
        pr += __shfl_down_sync(0xffffffffu, pr, o);
    if ((tid & 31) == 0) red[tid >> 5] = pr;
    __syncthreads();
    if (e == 0) {
        float y = red[i * 2] + red[i * 2 + 1] + (vred[0] + vred[1] + bv2[0]);
        float w = fabsf(y);
        if (w_out) w_out[b * NAG + i] = w;
        qpart[i] = w * agent_qs[b * NAG + i];
    }
    __syncthreads();
    if (tid == 0 && q_out) {
        float q = 0.f;
#pragma unroll
        for (int ii = 0; ii < NAG; ii++) q += qpart[ii];
        q_out[b] = q;
    }
}

// ===================== launch =====================
extern "C" void kernel_launch(void* const* d_in, const int* in_sizes, int n_in,
                              void* d_out, int out_size)
{
    const float* states    = (const float*)d_in[0];
    const float* actions   = (const float*)d_in[1];
    const float* agent_qs  = (const float*)d_in[2];
    const int*   gc        = (const int*)  d_in[4];
    const float* W1a = (const float*)d_in[5];
    const float* b1a = (const float*)d_in[6];
    const float* W1b = (const float*)d_in[7];
    const float* b1b = (const float*)d_in[8];
    const float* Wb  = (const float*)d_in[9];
    const float* bb  = (const float*)d_in[10];
    const float* Wfa = (const float*)d_in[11];
    const float* bfa = (const float*)d_in[12];
    const float* Wfb = (const float*)d_in[13];
    const float* bfb = (const float*)d_in[14];
    const float* Wv1 = (const float*)d_in[15];
    const float* bv1 = (const float*)d_in[16];
    const float* Wv2 = (const float*)d_in[17];
    const float* bv2 = (const float*)d_in[18];

    static bool inited = false;
    if (!inited) {
        cudaFuncSetAttribute(hmma_gemm, cudaFuncAttributeMaxDynamicSharedMemorySize, SMEM_HMMA);
        inited = true;
    }

    float* out = (float*)d_out;
    float* q_out = nullptr;
    float* w_out = nullptr;
    if (out_size == BATCH + BATCH * NAG)      { q_out = out; w_out = out + BATCH; }
    else if (out_size == BATCH * NAG)         { w_out = out; }
    else if (out_size == BATCH)               { q_out = out; }
    else                                      { q_out = out; w_out = out + BATCH; }

    trans_split<<<dim3(W1N / 32, HDIM / 32), 256>>>(W1b);
    gemm0_kernel<<<dim3(CATN / 64, BATCH / 64), 256>>>(states, W1a, b1a, Wfa, bfa,
                                                       Wb, bb, Wv1, bv1);
    coal_kernel<<<BATCH, 256>>>(actions, gc);
    wf_kernel<<<BATCH / 16, 256>>>(Wfb, bfb);
    hmma_gemm<<<dim3(W1N / 128, BATCH / 128), 256, SMEM_HMMA>>>(b1b);
    final_kernel<<<BATCH, 1024>>>(actions, Wv2, bv2, agent_qs, q_out, w_out);
}

// round 5
// speedup vs baseline: 2.6097x; 1.1319x over previous
#include <cuda_runtime.h>
#include <cuda_bf16.h>
#include <math.h>
#include <stdint.h>

// Problem constants
#define BATCH 2048      // B*T
#define NAG   16
#define NACT  20
#define DDIM  128
#define NSAMP 32
#define EDIM  64
#define HDIM  256
#define W1N   2560      // E*2*A
#define CATN  640       // 256(h1a)+256(hf)+64(b1)+64(vh)

// ---------------- scratch (device globals) ----------------
__device__ float g_out0[BATCH * CATN];
__device__ __nv_bfloat16 g_Ahi[BATCH * HDIM];
__device__ __nv_bfloat16 g_Alo[BATCH * HDIM];
__device__ __nv_bfloat16 g_Bhi[W1N * HDIM];
__device__ __nv_bfloat16 g_Blo[W1N * HDIM];
__device__ float g_w1 [BATCH * W1N];
__device__ float g_wf [BATCH * EDIM];
__device__ float g_coal[BATCH * NAG * NACT];

// ===================== PTX helpers =====================
__device__ __forceinline__ uint32_t smem_to_u32(const void* p) {
    uint32_t a;
    asm("{ .reg .u64 t; cvta.to.shared.u64 t, %1; cvt.u32.u64 %0, t; }" : "=r"(a) : "l"(p));
    return a;
}
#define LDMATRIX_X4(r, a) \
    asm volatile("ldmatrix.sync.aligned.m8n8.x4.shared.b16 {%0,%1,%2,%3}, [%4];" \
        : "=r"((r)[0]), "=r"((r)[1]), "=r"((r)[2]), "=r"((r)[3]) : "r"(a))
#define MMA16816(c, a, b0, b1) \
    asm volatile("mma.sync.aligned.m16n8k16.row.col.f32.bf16.bf16.f32 " \
        "{%0,%1,%2,%3},{%4,%5,%6,%7},{%8,%9},{%0,%1,%2,%3};" \
        : "+f"((c)[0]), "+f"((c)[1]), "+f"((c)[2]), "+f"((c)[3]) \
        : "r"((a)[0]), "r"((a)[1]), "r"((a)[2]), "r"((a)[3]), "r"(b0), "r"(b1))
#define CP_ASYNC16(dst, src) \
    asm volatile("cp.async.ca.shared.global [%0], [%1], 16;" :: "r"(dst), "l"(src))
#define CP_COMMIT() asm volatile("cp.async.commit_group;" ::: "memory")
#define CP_WAIT1()  asm volatile("cp.async.wait_group 1;" ::: "memory")
#define CP_WAIT0()  asm volatile("cp.async.wait_group 0;" ::: "memory")

// ======================================================================
// STAGE 1: trans_split + gemm0 + coal fused (grid-partitioned)
// ======================================================================
#define S1_GEMM0_BLKS 320
#define S1_TRANS_BLKS 640
#define S1_COAL_BLKS  BATCH
#define S1_TOTAL (S1_GEMM0_BLKS + S1_TRANS_BLKS + S1_COAL_BLKS)

// ---- gemm0: states[2048x128] @ [W1a|Wfa|Wb|Wv1], 64x64 tile ----
__device__ __forceinline__ void gemm0_block(
    int bx, char* smraw, const float* __restrict__ states,
    const float* __restrict__ W1a, const float* __restrict__ b1a,
    const float* __restrict__ Wfa, const float* __restrict__ bfa,
    const float* __restrict__ Wb,  const float* __restrict__ bb,
    const float* __restrict__ Wv1, const float* __restrict__ bv1)
{
    float* As = (float*)smraw;                  // [2][64][36] = 4608 floats
    float* Bs = (float*)(smraw + 4608 * 4);     // [2][32][64] = 4096 floats

    const int tid = threadIdx.x;
    const int n0 = (bx % 10) * 64;
    const int m0 = (bx / 10) * 64;
    const int tx = tid & 15, ty = tid >> 4;

    const float* Bsrc; const float* bias; int ldb; int nc0;
    if      (n0 < 256) { Bsrc = W1a; bias = b1a; ldb = 256; nc0 = n0; }
    else if (n0 < 512) { Bsrc = Wfa; bias = bfa; ldb = 256; nc0 = n0 - 256; }
    else if (n0 < 576) { Bsrc = Wb;  bias = bb;  ldb = 64;  nc0 = 0; }
    else               { Bsrc = Wv1; bias = bv1; ldb = 64;  nc0 = 0; }

    auto load_stage = [&](int s, int k0) {
#pragma unroll
        for (int j = 0; j < 2; j++) {
            int idx = tid * 2 + j;
            int row = idx >> 3, c = idx & 7;
            CP_ASYNC16(smem_to_u32(&As[s * 2304 + row * 36 + c * 4]),
                       states + (size_t)(m0 + row) * DDIM + k0 + c * 4);
        }
#pragma unroll
        for (int j = 0; j < 2; j++) {
            int idx = tid * 2 + j;
            int k = idx >> 4, c = idx & 15;
            CP_ASYNC16(smem_to_u32(&Bs[s * 2048 + k * 64 + c * 4]),
                       Bsrc + (size_t)(k0 + k) * ldb + nc0 + c * 4);
        }
    };

    float acc[4][4];
#pragma unroll
    for (int r = 0; r < 4; r++)
#pragma unroll
        for (int j = 0; j < 4; j++) acc[r][j] = 0.f;

    load_stage(0, 0);
    CP_COMMIT();

    for (int c = 0; c < 4; c++) {
        if (c < 3) { load_stage((c + 1) & 1, (c + 1) * 32); CP_COMMIT(); CP_WAIT1(); }
        else       { CP_WAIT0(); }
        __syncthreads();
        const int buf = c & 1;
#pragma unroll
        for (int kk = 0; kk < 32; kk++) {
            float av[4];
#pragma unroll
            for (int r = 0; r < 4; r++) av[r] = As[buf * 2304 + (ty * 4 + r) * 36 + kk];
            float4 bv = *(const float4*)&Bs[buf * 2048 + kk * 64 + tx * 4];
            float bw[4] = {bv.x, bv.y, bv.z, bv.w};
#pragma unroll
            for (int r = 0; r < 4; r++)
#pragma unroll
                for (int j = 0; j < 4; j++)
                    acc[r][j] += av[r] * bw[j];
        }
        __syncthreads();
    }

    const bool do_relu = (n0 != 512);
    float bs[4];
#pragma unroll
    for (int j = 0; j < 4; j++) bs[j] = bias[nc0 + tx * 4 + j];

#pragma unroll
    for (int r = 0; r < 4; r++) {
        int m = m0 + ty * 4 + r;
        float4 o;
        float* po = &o.x;
#pragma unroll
        for (int j = 0; j < 4; j++) {
            float v = acc[r][j] + bs[j];
            if (do_relu) v = fmaxf(v, 0.f);
            po[j] = v;
        }
        *(float4*)&g_out0[(size_t)m * CATN + n0 + tx * 4] = o;
        if (n0 < 256) {
            __nv_bfloat16 h[4]; float lo[4];
#pragma unroll
            for (int j = 0; j < 4; j++) {
                h[j] = __float2bfloat16(po[j]);
                lo[j] = po[j] - __bfloat162float(h[j]);
            }
            size_t base = (size_t)m * HDIM + n0 + tx * 4;
            *(__nv_bfloat162*)&g_Ahi[base]     = __nv_bfloat162(h[0], h[1]);
            *(__nv_bfloat162*)&g_Ahi[base + 2] = __nv_bfloat162(h[2], h[3]);
            *(__nv_bfloat162*)&g_Alo[base]     = __nv_bfloat162(__float2bfloat16(lo[0]), __float2bfloat16(lo[1]));
            *(__nv_bfloat162*)&g_Alo[base + 2] = __nv_bfloat162(__float2bfloat16(lo[2]), __float2bfloat16(lo[3]));
        }
    }
}

// ---- trans_split: W1b [256x2560] -> bf16 hi/lo [2560x256] ----
__device__ __forceinline__ void trans_block(int t, char* smraw, const float* __restrict__ W1b)
{
    float* ts = (float*)smraw;      // [32][33]
    int n0 = (t % 80) * 32, k0 = (t / 80) * 32;
    int tx = threadIdx.x & 31, ty = threadIdx.x >> 5;   // 32 x 8
#pragma unroll
    for (int r = 0; r < 4; r++)
        ts[(ty * 4 + r) * 33 + tx] = W1b[(size_t)(k0 + ty * 4 + r) * W1N + n0 + tx];
    __syncthreads();
#pragma unroll
    for (int r = 0; r < 4; r++) {
        int n = n0 + ty * 4 + r, k = k0 + tx;
        float v = ts[tx * 33 + ty * 4 + r];
        __nv_bfloat16 hi = __float2bfloat16(v);
        float lof = v - __bfloat162float(hi);
        g_Bhi[(size_t)n * HDIM + k] = hi;
        g_Blo[(size_t)n * HDIM + k] = __float2bfloat16(lof);
    }
}

// ---- coal: sync-free per-warp samples ----
__device__ __forceinline__ void coal_block(int b, char* smraw,
    const float* __restrict__ actions, const int* __restrict__ gc)
{
    float* act_s = (float*)smraw;                    // 320
    int*   gcs   = (int*)(smraw + 320 * 4);          // 512
    float* sbuf  = (float*)(smraw + 320 * 4 + 512 * 4);  // [8][320]

    const int tid = threadIdx.x;
    const int w = tid >> 5, a = tid & 31;

    for (int idx = tid; idx < NAG * NACT; idx += 256)
        act_s[idx] = actions[b * NAG * NACT + idx];
    for (int idx = tid; idx < NSAMP * NAG; idx += 256)
        gcs[idx] = gc[b * NSAMP * NAG + idx];
    __syncthreads();

    float accp[NAG];
#pragma unroll
    for (int i = 0; i < NAG; i++) accp[i] = 0.f;

#pragma unroll
    for (int si = 0; si < 4; si++) {
        const int s = w * 4 + si;
        float q = 0.f;
#pragma unroll
        for (int m = 0; m < NAG; m++) {
            int g = gcs[s * NAG + m];
            if (a < NACT) {
                sbuf[w * 320 + m * NACT + a] = q;
                q += act_s[g * NACT + a];
            }
        }
#pragma unroll
        for (int i = 0; i < NAG; i++) {
            int g = gcs[s * NAG + i];
            if (a < NACT) accp[i] += (float)g * sbuf[w * 320 + g * NACT + a];
        }
    }
    if (a < NACT) {
#pragma unroll
        for (int i = 0; i < NAG; i++) sbuf[w * 320 + i * NACT + a] = accp[i];
    }
    __syncthreads();
    for (int idx = tid; idx < NAG * NACT; idx += 256) {
        float s = 0.f;
#pragma unroll
        for (int w8 = 0; w8 < 8; w8++) s += sbuf[w8 * 320 + idx];
        g_coal[b * NAG * NACT + idx] = s * (1.f / 512.f);
    }
}

__global__ void __launch_bounds__(256)
stage1_kernel(const float* __restrict__ states,
              const float* __restrict__ W1a, const float* __restrict__ b1a,
              const float* __restrict__ Wfa, const float* __restrict__ bfa,
              const float* __restrict__ Wb,  const float* __restrict__ bb,
              const float* __restrict__ Wv1, const float* __restrict__ bv1,
              const float* __restrict__ W1b,
              const float* __restrict__ actions, const int* __restrict__ gc)
{
    __shared__ __align__(16) char sm1[34816];
    const int bx = blockIdx.x;
    if (bx < S1_GEMM0_BLKS) {
        gemm0_block(bx, sm1, states, W1a, b1a, Wfa, bfa, Wb, bb, Wv1, bv1);
    } else if (bx < S1_GEMM0_BLKS + S1_TRANS_BLKS) {
        trans_block(bx - S1_GEMM0_BLKS, sm1, W1b);
    } else {
        coal_block(bx - S1_GEMM0_BLKS - S1_TRANS_BLKS, sm1, actions, gc);
    }
}

// ======================================================================
// STAGE 2: hmma (320 blocks) + wf (128 blocks) fused
// ======================================================================
#define T_ROWB   80
#define T_BYTES  (128 * T_ROWB)
#define STAGE_B  (4 * T_BYTES)
#define SMEM_S2  (2 * STAGE_B)    // 81920

__device__ __forceinline__ void hmma_block(int bx, char* sm, const float* __restrict__ b1b)
{
    const int tid = threadIdx.x;
    const int wid = tid >> 5, lane = tid & 31;
    const int n0 = (bx % 20) * 128;
    const int m0 = (bx / 20) * 128;
    const int wm = (wid >> 2) * 64;
    const int wn = (wid & 3) * 32;

    float acc[4][4][4];
#pragma unroll
    for (int r = 0; r < 4; r++)
#pragma unroll
        for (int g = 0; g < 4; g++)
#pragma unroll
            for (int c = 0; c < 4; c++) acc[r][g][c] = 0.f;

    const __nv_bfloat16* srcs[4] = {g_Ahi, g_Alo, g_Bhi, g_Blo};

    auto load_stage = [&](int s, int k0) {
#pragma unroll
        for (int t = 0; t < 4; t++) {
            const int r0 = (t < 2) ? m0 : n0;
            const __nv_bfloat16* src = srcs[t];
            char* dstb = sm + s * STAGE_B + t * T_BYTES;
#pragma unroll
            for (int j = 0; j < 2; j++) {
                int idx = tid + j * 256;
                int row = idx >> 2, c = idx & 3;
                CP_ASYNC16(smem_to_u32(dstb + row * T_ROWB + c * 16),
                           (const char*)(src + (size_t)(r0 + row) * HDIM + k0) + c * 16);
            }
        }
    };

    load_stage(0, 0);
    CP_COMMIT();

    for (int kc = 0; kc < 8; kc++) {
        if (kc < 7) { load_stage((kc + 1) & 1, (kc + 1) * 32); CP_COMMIT(); CP_WAIT1(); }
        else        { CP_WAIT0(); }
        __syncthreads();

        char* Ah = sm + (kc & 1) * STAGE_B;
        char* Al = Ah + T_BYTES;
        char* Bh = Ah + 2 * T_BYTES;
        char* Bl = Ah + 3 * T_BYTES;

#pragma unroll
        for (int ks = 0; ks < 2; ks++) {
            const int kb = ks * 32;
            uint32_t ah[4][4], al[4][4], bh[2][4], bl[2][4];
            const int arow = wm + (lane & 15);
            const int akb  = kb + (lane >> 4) * 16;
#pragma unroll
            for (int r = 0; r < 4; r++) {
                LDMATRIX_X4(ah[r], smem_to_u32(Ah + (arow + r * 16) * T_ROWB + akb));
                LDMATRIX_X4(al[r], smem_to_u32(Al + (arow + r * 16) * T_ROWB + akb));
            }
            const int brow = wn + (lane & 7) + (lane >> 4) * 8;
            const int bkb  = kb + ((lane >> 3) & 1) * 16;
#pragma unroll
            for (int g = 0; g < 2; g++) {
                LDMATRIX_X4(bh[g], smem_to_u32(Bh + (brow + g * 16) * T_ROWB + bkb));
                LDMATRIX_X4(bl[g], smem_to_u32(Bl + (brow + g * 16) * T_ROWB + bkb));
            }
#pragma unroll
            for (int r = 0; r < 4; r++)
#pragma unroll
                for (int g = 0; g < 4; g++) {
                    uint32_t b0h = bh[g >> 1][(g & 1) * 2], b1h = bh[g >> 1][(g & 1) * 2 + 1];
                    uint32_t b0l = bl[g >> 1][(g & 1) * 2], b1l = bl[g >> 1][(g & 1) * 2 + 1];
                    MMA16816(acc[r][g], ah[r], b0h, b1h);
                    MMA16816(acc[r][g], ah[r], b0l, b1l);
                    MMA16816(acc[r][g], al[r], b0h, b1h);
                }
        }
        __syncthreads();
    }

    const int mrow  = m0 + wm + (lane >> 2);
    const int ncol0 = n0 + wn + (lane & 3) * 2;
#pragma unroll
    for (int g = 0; g < 4; g++) {
        const int n = ncol0 + g * 8;
        float2 bias = *(const float2*)&b1b[n];
#pragma unroll
        for (int r = 0; r < 4; r++) {
            const int m = mrow + r * 16;
            float2 o0, o1;
            o0.x = fabsf(acc[r][g][0] + bias.x);
            o0.y = fabsf(acc[r][g][1] + bias.y);
            o1.x = fabsf(acc[r][g][2] + bias.x);
            o1.y = fabsf(acc[r][g][3] + bias.y);
            *(float2*)&g_w1[(size_t)m * W1N + n]       = o0;
            *(float2*)&g_w1[(size_t)(m + 8) * W1N + n] = o1;
        }
    }
}

__device__ __forceinline__ void wf_block(int wb, char* sm,
    const float* __restrict__ Wfb, const float* __restrict__ bfb)
{
    float* As = (float*)sm;             // [2][16][36]
    float* Bs = (float*)(sm + 4608);    // [2][32][64]
    const int tid = threadIdx.x;
    const int m0 = wb * 16;
    const int tx = tid & 15, ty = tid >> 4;

    auto load_stage = [&](int s, int k0) {
        if (tid < 128) {
            int row = tid >> 3, c = tid & 7;
            CP_ASYNC16(smem_to_u32(&As[s * 576 + row * 36 + c * 4]),
                       g_out0 + (size_t)(m0 + row) * CATN + 256 + k0 + c * 4);
        }
#pragma unroll
        for (int j = 0; j < 2; j++) {
            int idx = tid * 2 + j;
            int k = idx >> 4, c = idx & 15;
            CP_ASYNC16(smem_to_u32(&Bs[s * 2048 + k * 64 + c * 4]),
                       Wfb + (size_t)(k0 + k) * EDIM + c * 4);
        }
    };

    float acc[4] = {0.f, 0.f, 0.f, 0.f};
    load_stage(0, 0);
    CP_COMMIT();

    for (int c = 0; c < 8; c++) {
        if (c < 7) { load_stage((c + 1) & 1, (c + 1) * 32); CP_COMMIT(); CP_WAIT1(); }
        else       { CP_WAIT0(); }
        __syncthreads();
        const int buf = c & 1;
#pragma unroll
        for (int kk = 0; kk < 32; kk++) {
            float a = As[buf * 576 + ty * 36 + kk];
            float4 bv = *(const float4*)&Bs[buf * 2048 + kk * 64 + tx * 4];
            acc[0] += a * bv.x; acc[1] += a * bv.y;
            acc[2] += a * bv.z; acc[3] += a * bv.w;
        }
        __syncthreads();
    }

    float4 bsv = *(const float4*)&bfb[tx * 4];
    float4 o;
    o.x = fabsf(acc[0] + bsv.x);
    o.y = fabsf(acc[1] + bsv.y);
    o.z = fabsf(acc[2] + bsv.z);
    o.w = fabsf(acc[3] + bsv.w);
    *(float4*)&g_wf[(size_t)(m0 + ty) * EDIM + tx * 4] = o;
}

__global__ void __launch_bounds__(256)
stage2_kernel(const float* __restrict__ b1b,
              const float* __restrict__ Wfb, const float* __restrict__ bfb)
{
    extern __shared__ char sm[];
    const int bx = blockIdx.x;
    if (bx < 320) hmma_block(bx, sm, b1b);
    else          wf_block(bx - 320, sm, Wfb, bfb);
}

// ======================================================================
// STAGE 3: final mix (v fused)
// ======================================================================
__global__ void __launch_bounds__(1024)
final_kernel(const float* __restrict__ actions, const float* __restrict__ Wv2,
             const float* __restrict__ bv2, const float* __restrict__ agent_qs,
             float* __restrict__ q_out, float* __restrict__ w_out)
{
    int b = blockIdx.x;
    int tid = threadIdx.x;
    int i = tid >> 6, e = tid & 63;

    __shared__ float w1s[W1N];
    __shared__ float ins[NAG][40];
    __shared__ float wfs[EDIM], b1s[EDIM];
    __shared__ float red[32], vred[2];
    __shared__ float qpart[NAG];

    if (tid < 640)
        ((float4*)w1s)[tid] = ((const float4*)(g_w1 + (size_t)b * W1N))[tid];
    if (tid < 320)
        ins[tid / NACT][tid % NACT] = g_coal[b * NAG * NACT + tid];
    else if (tid < 640) {
        int t = tid - 320;
        ins[t / NACT][NACT + t % NACT] = actions[b * NAG * NACT + t];
    } else if (tid < 704) {
        int ee = tid - 640;
        float pv = g_out0[(size_t)b * CATN + 576 + ee] * Wv2[ee];
#pragma unroll
        for (int o = 16; o > 0; o >>= 1)
            pv += __shfl_down_sync(0xffffffffu, pv, o);
        if ((ee & 31) == 0) vred[ee >> 5] = pv;
    } else if (tid < 768) {
        wfs[tid - 704] = g_wf[(size_t)b * EDIM + tid - 704];
    } else if (tid < 832) {
        b1s[tid - 768] = g_out0[(size_t)b * CATN + 512 + (tid - 768)];
    }
    __syncthreads();

    float h = b1s[e];
#pragma unroll
    for (int k = 0; k < 40; k++)
        h += ins[i][k] * w1s[k * EDIM + e];
    float hid = h > 0.f ? h : expm1f(h);
    float pr = hid * wfs[e];
#pragma unroll
    for (int o = 16; o > 0; o >>= 1)
        pr += __shfl_down_sync(0xffffffffu, pr, o);
    if ((tid & 31) == 0) red[tid >> 5] = pr;
    __syncthreads();
    if (e == 0) {
        float y = red[i * 2] + red[i * 2 + 1] + (vred[0] + vred[1] + bv2[0]);
        float w = fabsf(y);
        if (w_out) w_out[b * NAG + i] = w;
        qpart[i] = w * agent_qs[b * NAG + i];
    }
    __syncthreads();
    if (tid == 0 && q_out) {
        float q = 0.f;
#pragma unroll
        for (int ii = 0; ii < NAG; ii++) q += qpart[ii];
        q_out[b] = q;
    }
}

// ======================================================================
// launch
// ======================================================================
extern "C" void kernel_launch(void* const* d_in, const int* in_sizes, int n_in,
                              void* d_out, int out_size)
{
    const float* states    = (const float*)d_in[0];
    const float* actions   = (const float*)d_in[1];
    const float* agent_qs  = (const float*)d_in[2];
    const int*   gc        = (const int*)  d_in[4];
    const float* W1a = (const float*)d_in[5];
    const float* b1a = (const float*)d_in[6];
    const float* W1b = (const float*)d_in[7];
    const float* b1b = (const float*)d_in[8];
    const float* Wb  = (const float*)d_in[9];
    const float* bb  = (const float*)d_in[10];
    const float* Wfa = (const float*)d_in[11];
    const float* bfa = (const float*)d_in[12];
    const float* Wfb = (const float*)d_in[13];
    const float* bfb = (const float*)d_in[14];
    const float* Wv1 = (const float*)d_in[15];
    const float* bv1 = (const float*)d_in[16];
    const float* Wv2 = (const float*)d_in[17];
    const float* bv2 = (const float*)d_in[18];

    static bool inited = false;
    if (!inited) {
        cudaFuncSetAttribute(stage2_kernel, cudaFuncAttributeMaxDynamicSharedMemorySize, SMEM_S2);
        inited = true;
    }

    float* out = (float*)d_out;
    float* q_out = nullptr;
    float* w_out = nullptr;
    if (out_size == BATCH + BATCH * NAG)      { q_out = out; w_out = out + BATCH; }
    else if (out_size == BATCH * NAG)         { w_out = out; }
    else if (out_size == BATCH)               { q_out = out; }
    else                                      { q_out = out; w_out = out + BATCH; }

    stage1_kernel<<<S1_TOTAL, 256>>>(states, W1a, b1a, Wfa, bfa, Wb, bb, Wv1, bv1,
                                     W1b, actions, gc);
    stage2_kernel<<<320 + 128, 256, SMEM_S2>>>(b1b, Wfb, bfb);
    final_kernel<<<BATCH, 1024>>>(actions, Wv2, bv2, agent_qs, q_out, w_out);
}

// round 6
// speedup vs baseline: 3.2543x; 1.2470x over previous
#include <cuda_runtime.h>
#include <cuda_bf16.h>
#include <math.h>
#include <stdint.h>

// Problem constants
#define BATCH 2048      // B*T
#define NAG   16
#define NACT  20
#define DDIM  128
#define NSAMP 32
#define EDIM  64
#define HDIM  256
#define W1N   2560      // E*2*A
#define CATN  640       // 256(h1a)+256(hf)+64(b1)+64(vh)

// ---------------- scratch (device globals) ----------------
__device__ float g_out0[BATCH * CATN];
__device__ __nv_bfloat16 g_Ahi[BATCH * HDIM];
__device__ __nv_bfloat16 g_Alo[BATCH * HDIM];
__device__ __nv_bfloat16 g_Bhi[W1N * HDIM];
__device__ __nv_bfloat16 g_Blo[W1N * HDIM];
__device__ float g_w1 [BATCH * W1N];
__device__ float g_wf [BATCH * EDIM];
__device__ float g_coal[BATCH * NAG * NACT];

// ===================== PTX helpers =====================
__device__ __forceinline__ uint32_t smem_to_u32(const void* p) {
    uint32_t a;
    asm("{ .reg .u64 t; cvta.to.shared.u64 t, %1; cvt.u32.u64 %0, t; }" : "=r"(a) : "l"(p));
    return a;
}
#define LDMATRIX_X4(r, a) \
    asm volatile("ldmatrix.sync.aligned.m8n8.x4.shared.b16 {%0,%1,%2,%3}, [%4];" \
        : "=r"((r)[0]), "=r"((r)[1]), "=r"((r)[2]), "=r"((r)[3]) : "r"(a))
#define MMA16816(c, a, b0, b1) \
    asm volatile("mma.sync.aligned.m16n8k16.row.col.f32.bf16.bf16.f32 " \
        "{%0,%1,%2,%3},{%4,%5,%6,%7},{%8,%9},{%0,%1,%2,%3};" \
        : "+f"((c)[0]), "+f"((c)[1]), "+f"((c)[2]), "+f"((c)[3]) \
        : "r"((a)[0]), "r"((a)[1]), "r"((a)[2]), "r"((a)[3]), "r"(b0), "r"(b1))
#define CP_ASYNC16(dst, src) \
    asm volatile("cp.async.cg.shared.global [%0], [%1], 16;" :: "r"(dst), "l"(src))
#define CP_COMMIT() asm volatile("cp.async.commit_group;" ::: "memory")
#define CP_WAIT1()  asm volatile("cp.async.wait_group 1;" ::: "memory")
#define CP_WAIT0()  asm volatile("cp.async.wait_group 0;" ::: "memory")

// ======================================================================
// STAGE 1: gemm0 + trans_split + coal fused (grid-partitioned)
// ======================================================================
#define S1_GEMM0_BLKS 320
#define S1_TRANS_BLKS 640
#define S1_COAL_BLKS  BATCH
#define S1_TOTAL (S1_GEMM0_BLKS + S1_TRANS_BLKS + S1_COAL_BLKS)

// ---- gemm0: states[2048x128] @ [W1a|Wfa|Wb|Wv1], 64x64 tile ----
__device__ __forceinline__ void gemm0_block(
    int bx, char* smraw, const float* __restrict__ states,
    const float* __restrict__ W1a, const float* __restrict__ b1a,
    const float* __restrict__ Wfa, const float* __restrict__ bfa,
    const float* __restrict__ Wb,  const float* __restrict__ bb,
    const float* __restrict__ Wv1, const float* __restrict__ bv1)
{
    float* As = (float*)smraw;                  // [2][64][36]
    float* Bs = (float*)(smraw + 4608 * 4);     // [2][32][64]

    const int tid = threadIdx.x;
    const int n0 = (bx % 10) * 64;
    const int m0 = (bx / 10) * 64;
    const int tx = tid & 15, ty = tid >> 4;

    const float* Bsrc; const float* bias; int ldb; int nc0;
    if      (n0 < 256) { Bsrc = W1a; bias = b1a; ldb = 256; nc0 = n0; }
    else if (n0 < 512) { Bsrc = Wfa; bias = bfa; ldb = 256; nc0 = n0 - 256; }
    else if (n0 < 576) { Bsrc = Wb;  bias = bb;  ldb = 64;  nc0 = 0; }
    else               { Bsrc = Wv1; bias = bv1; ldb = 64;  nc0 = 0; }

    auto load_stage = [&](int s, int k0) {
#pragma unroll
        for (int j = 0; j < 2; j++) {
            int idx = tid * 2 + j;
            int row = idx >> 3, c = idx & 7;
            CP_ASYNC16(smem_to_u32(&As[s * 2304 + row * 36 + c * 4]),
                       states + (size_t)(m0 + row) * DDIM + k0 + c * 4);
        }
#pragma unroll
        for (int j = 0; j < 2; j++) {
            int idx = tid * 2 + j;
            int k = idx >> 4, c = idx & 15;
            CP_ASYNC16(smem_to_u32(&Bs[s * 2048 + k * 64 + c * 4]),
                       Bsrc + (size_t)(k0 + k) * ldb + nc0 + c * 4);
        }
    };

    float acc[4][4];
#pragma unroll
    for (int r = 0; r < 4; r++)
#pragma unroll
        for (int j = 0; j < 4; j++) acc[r][j] = 0.f;

    load_stage(0, 0);
    CP_COMMIT();

    for (int c = 0; c < 4; c++) {
        if (c < 3) { load_stage((c + 1) & 1, (c + 1) * 32); CP_COMMIT(); CP_WAIT1(); }
        else       { CP_WAIT0(); }
        __syncthreads();
        const int buf = c & 1;
#pragma unroll
        for (int kk = 0; kk < 32; kk++) {
            float av[4];
#pragma unroll
            for (int r = 0; r < 4; r++) av[r] = As[buf * 2304 + (ty * 4 + r) * 36 + kk];
            float4 bv = *(const float4*)&Bs[buf * 2048 + kk * 64 + tx * 4];
            float bw[4] = {bv.x, bv.y, bv.z, bv.w};
#pragma unroll
            for (int r = 0; r < 4; r++)
#pragma unroll
                for (int j = 0; j < 4; j++)
                    acc[r][j] += av[r] * bw[j];
        }
        __syncthreads();
    }

    const bool do_relu = (n0 != 512);
    float bs[4];
#pragma unroll
    for (int j = 0; j < 4; j++) bs[j] = bias[nc0 + tx * 4 + j];

#pragma unroll
    for (int r = 0; r < 4; r++) {
        int m = m0 + ty * 4 + r;
        float4 o;
        float* po = &o.x;
#pragma unroll
        for (int j = 0; j < 4; j++) {
            float v = acc[r][j] + bs[j];
            if (do_relu) v = fmaxf(v, 0.f);
            po[j] = v;
        }
        *(float4*)&g_out0[(size_t)m * CATN + n0 + tx * 4] = o;
        if (n0 < 256) {
            __nv_bfloat16 h[4]; float lo[4];
#pragma unroll
            for (int j = 0; j < 4; j++) {
                h[j] = __float2bfloat16(po[j]);
                lo[j] = po[j] - __bfloat162float(h[j]);
            }
            size_t base = (size_t)m * HDIM + n0 + tx * 4;
            *(__nv_bfloat162*)&g_Ahi[base]     = __nv_bfloat162(h[0], h[1]);
            *(__nv_bfloat162*)&g_Ahi[base + 2] = __nv_bfloat162(h[2], h[3]);
            *(__nv_bfloat162*)&g_Alo[base]     = __nv_bfloat162(__float2bfloat16(lo[0]), __float2bfloat16(lo[1]));
            *(__nv_bfloat162*)&g_Alo[base + 2] = __nv_bfloat162(__float2bfloat16(lo[2]), __float2bfloat16(lo[3]));
        }
    }
}

// ---- trans_split: W1b [256x2560] -> bf16 hi/lo [2560x256] ----
__device__ __forceinline__ void trans_block(int t, char* smraw, const float* __restrict__ W1b)
{
    float* ts = (float*)smraw;      // [32][33]
    int n0 = (t % 80) * 32, k0 = (t / 80) * 32;
    int tx = threadIdx.x & 31, ty = threadIdx.x >> 5;   // 32 x 8
#pragma unroll
    for (int r = 0; r < 4; r++)
        ts[(ty * 4 + r) * 33 + tx] = W1b[(size_t)(k0 + ty * 4 + r) * W1N + n0 + tx];
    __syncthreads();
#pragma unroll
    for (int r = 0; r < 4; r++) {
        int n = n0 + ty * 4 + r, k = k0 + tx;
        float v = ts[tx * 33 + ty * 4 + r];
        __nv_bfloat16 hi = __float2bfloat16(v);
        float lof = v - __bfloat162float(hi);
        g_Bhi[(size_t)n * HDIM + k] = hi;
        g_Blo[(size_t)n * HDIM + k] = __float2bfloat16(lof);
    }
}

// ---- coal: exact integer weight-matrix formulation ----
// gc[b,s,:] is a permutation of 0..15.
// W[i][m] = sum_s g_{s,i} * 1[inv_s(m) < g_{s,i}],  coal = (1/512) W @ act.
__device__ __forceinline__ void coal_block(int b, char* smraw,
    const float* __restrict__ actions, const int* __restrict__ gc)
{
    int*   gcs   = (int*)smraw;              // [32][16]
    int*   inv   = gcs + 512;                // [32][16]
    float* act_s = (float*)(inv + 512);      // [16][20]
    float* Ws    = act_s + 320;              // [16][16]

    const int tid = threadIdx.x;

    for (int idx = tid; idx < 512; idx += 256)
        gcs[idx] = gc[b * 512 + idx];
    for (int idx = tid; idx < 320; idx += 256)
        act_s[idx] = actions[b * 320 + idx];
    __syncthreads();

    // inverse permutations: thread (s, pos) for s in {t>>4, t>>4 + 16}
    {
        int s = tid >> 4, pos = tid & 15;
        int v0 = gcs[s * 16 + pos];
        inv[s * 16 + v0] = pos;
        int v1 = gcs[(s + 16) * 16 + pos];
        inv[(s + 16) * 16 + v1] = pos;
    }
    __syncthreads();

    // W accumulation: thread (i, m)
    {
        int i = tid >> 4, m = tid & 15;
        int w = 0;
#pragma unroll
        for (int s = 0; s < 32; s++) {
            int gi = gcs[s * 16 + i];
            int pm = inv[s * 16 + m];
            w += (pm < gi) ? gi : 0;
        }
        Ws[i * 16 + m] = (float)w;
    }
    __syncthreads();

    // coal = (1/512) W @ act : thread (i, c) handles a = c (+16)
    {
        int i = tid >> 4, c = tid & 15;
        for (int a = c; a < NACT; a += 16) {
            float sum = 0.f;
#pragma unroll
            for (int m = 0; m < 16; m++)
                sum += Ws[i * 16 + m] * act_s[m * NACT + a];
            g_coal[b * 320 + i * NACT + a] = sum * (1.f / 512.f);
        }
    }
}

__global__ void __launch_bounds__(256)
stage1_kernel(const float* __restrict__ states,
              const float* __restrict__ W1a, const float* __restrict__ b1a,
              const float* __restrict__ Wfa, const float* __restrict__ bfa,
              const float* __restrict__ Wb,  const float* __restrict__ bb,
              const float* __restrict__ Wv1, const float* __restrict__ bv1,
              const float* __restrict__ W1b,
              const float* __restrict__ actions, const int* __restrict__ gc)
{
    __shared__ __align__(16) char sm1[34816];
    const int bx = blockIdx.x;
    if (bx < S1_GEMM0_BLKS) {
        gemm0_block(bx, sm1, states, W1a, b1a, Wfa, bfa, Wb, bb, Wv1, bv1);
    } else if (bx < S1_GEMM0_BLKS + S1_TRANS_BLKS) {
        trans_block(bx - S1_GEMM0_BLKS, sm1, W1b);
    } else {
        coal_block(bx - S1_GEMM0_BLKS - S1_TRANS_BLKS, sm1, actions, gc);
    }
}

// ======================================================================
// STAGE 2: hmma (320 blocks) + wf (128 blocks) fused
// ======================================================================
#define T_ROWB   80
#define T_BYTES  (128 * T_ROWB)
#define STAGE_B  (4 * T_BYTES)
#define SMEM_S2  (2 * STAGE_B)    // 81920

__device__ __forceinline__ void hmma_block(int bx, char* sm, const float* __restrict__ b1b)
{
    const int tid = threadIdx.x;
    const int wid = tid >> 5, lane = tid & 31;
    const int n0 = (bx % 20) * 128;
    const int m0 = (bx / 20) * 128;
    const int wm = (wid >> 2) * 64;
    const int wn = (wid & 3) * 32;

    float acc[4][4][4];
#pragma unroll
    for (int r = 0; r < 4; r++)
#pragma unroll
        for (int g = 0; g < 4; g++)
#pragma unroll
            for (int c = 0; c < 4; c++) acc[r][g][c] = 0.f;

    const __nv_bfloat16* srcs[4] = {g_Ahi, g_Alo, g_Bhi, g_Blo};

    auto load_stage = [&](int s, int k0) {
#pragma unroll
        for (int t = 0; t < 4; t++) {
            const int r0 = (t < 2) ? m0 : n0;
            const __nv_bfloat16* src = srcs[t];
            char* dstb = sm + s * STAGE_B + t * T_BYTES;
#pragma unroll
            for (int j = 0; j < 2; j++) {
                int idx = tid + j * 256;
                int row = idx >> 2, c = idx & 3;
                CP_ASYNC16(smem_to_u32(dstb + row * T_ROWB + c * 16),
                           (const char*)(src + (size_t)(r0 + row) * HDIM + k0) + c * 16);
            }
        }
    };

    load_stage(0, 0);
    CP_COMMIT();

    for (int kc = 0; kc < 8; kc++) {
        if (kc < 7) { load_stage((kc + 1) & 1, (kc + 1) * 32); CP_COMMIT(); CP_WAIT1(); }
        else        { CP_WAIT0(); }
        __syncthreads();

        char* Ah = sm + (kc & 1) * STAGE_B;
        char* Al = Ah + T_BYTES;
        char* Bh = Ah + 2 * T_BYTES;
        char* Bl = Ah + 3 * T_BYTES;

#pragma unroll
        for (int ks = 0; ks < 2; ks++) {
            const int kb = ks * 32;
            uint32_t ah[4][4], al[4][4], bh[2][4], bl[2][4];
            const int arow = wm + (lane & 15);
            const int akb  = kb + (lane >> 4) * 16;
#pragma unroll
            for (int r = 0; r < 4; r++) {
                LDMATRIX_X4(ah[r], smem_to_u32(Ah + (arow + r * 16) * T_ROWB + akb));
                LDMATRIX_X4(al[r], smem_to_u32(Al + (arow + r * 16) * T_ROWB + akb));
            }
            const int brow = wn + (lane & 7) + (lane >> 4) * 8;
            const int bkb  = kb + ((lane >> 3) & 1) * 16;
#pragma unroll
            for (int g = 0; g < 2; g++) {
                LDMATRIX_X4(bh[g], smem_to_u32(Bh + (brow + g * 16) * T_ROWB + bkb));
                LDMATRIX_X4(bl[g], smem_to_u32(Bl + (brow + g * 16) * T_ROWB + bkb));
            }
#pragma unroll
            for (int r = 0; r < 4; r++)
#pragma unroll
                for (int g = 0; g < 4; g++) {
                    uint32_t b0h = bh[g >> 1][(g & 1) * 2], b1h = bh[g >> 1][(g & 1) * 2 + 1];
                    uint32_t b0l = bl[g >> 1][(g & 1) * 2], b1l = bl[g >> 1][(g & 1) * 2 + 1];
                    MMA16816(acc[r][g], ah[r], b0h, b1h);
                    MMA16816(acc[r][g], ah[r], b0l, b1l);
                    MMA16816(acc[r][g], al[r], b0h, b1h);
                }
        }
        __syncthreads();
    }

    const int mrow  = m0 + wm + (lane >> 2);
    const int ncol0 = n0 + wn + (lane & 3) * 2;
#pragma unroll
    for (int g = 0; g < 4; g++) {
        const int n = ncol0 + g * 8;
        float2 bias = *(const float2*)&b1b[n];
#pragma unroll
        for (int r = 0; r < 4; r++) {
            const int m = mrow + r * 16;
            float2 o0, o1;
            o0.x = fabsf(acc[r][g][0] + bias.x);
            o0.y = fabsf(acc[r][g][1] + bias.y);
            o1.x = fabsf(acc[r][g][2] + bias.x);
            o1.y = fabsf(acc[r][g][3] + bias.y);
            *(float2*)&g_w1[(size_t)m * W1N + n]       = o0;
            *(float2*)&g_w1[(size_t)(m + 8) * W1N + n] = o1;
        }
    }
}

__device__ __forceinline__ void wf_block(int wb, char* sm,
    const float* __restrict__ Wfb, const float* __restrict__ bfb)
{
    float* As = (float*)sm;             // [2][16][36]
    float* Bs = (float*)(sm + 4608);    // [2][32][64]
    const int tid = threadIdx.x;
    const int m0 = wb * 16;
    const int tx = tid & 15, ty = tid >> 4;

    auto load_stage = [&](int s, int k0) {
        if (tid < 128) {
            int row = tid >> 3, c = tid & 7;
            CP_ASYNC16(smem_to_u32(&As[s * 576 + row * 36 + c * 4]),
                       g_out0 + (size_t)(m0 + row) * CATN + 256 + k0 + c * 4);
        }
#pragma unroll
        for (int j = 0; j < 2; j++) {
            int idx = tid * 2 + j;
            int k = idx >> 4, c = idx & 15;
            CP_ASYNC16(smem_to_u32(&Bs[s * 2048 + k * 64 + c * 4]),
                       Wfb + (size_t)(k0 + k) * EDIM + c * 4);
        }
    };

    float acc[4] = {0.f, 0.f, 0.f, 0.f};
    load_stage(0, 0);
    CP_COMMIT();

    for (int c = 0; c < 8; c++) {
        if (c < 7) { load_stage((c + 1) & 1, (c + 1) * 32); CP_COMMIT(); CP_WAIT1(); }
        else       { CP_WAIT0(); }
        __syncthreads();
        const int buf = c & 1;
#pragma unroll
        for (int kk = 0; kk < 32; kk++) {
            float a = As[buf * 576 + ty * 36 + kk];
            float4 bv = *(const float4*)&Bs[buf * 2048 + kk * 64 + tx * 4];
            acc[0] += a * bv.x; acc[1] += a * bv.y;
            acc[2] += a * bv.z; acc[3] += a * bv.w;
        }
        __syncthreads();
    }

    float4 bsv = *(const float4*)&bfb[tx * 4];
    float4 o;
    o.x = fabsf(acc[0] + bsv.x);
    o.y = fabsf(acc[1] + bsv.y);
    o.z = fabsf(acc[2] + bsv.z);
    o.w = fabsf(acc[3] + bsv.w);
    *(float4*)&g_wf[(size_t)(m0 + ty) * EDIM + tx * 4] = o;
}

__global__ void __launch_bounds__(256)
stage2_kernel(const float* __restrict__ b1b,
              const float* __restrict__ Wfb, const float* __restrict__ bfb)
{
    extern __shared__ char sm[];
    const int bx = blockIdx.x;
    if (bx < 320) hmma_block(bx, sm, b1b);
    else          wf_block(bx - 320, sm, Wfb, bfb);
}

// ======================================================================
// STAGE 3: final mix (v fused), 256 threads, 4 e-cols per thread
// ======================================================================
__global__ void __launch_bounds__(256)
final_kernel(const float* __restrict__ actions, const float* __restrict__ Wv2,
             const float* __restrict__ bv2, const float* __restrict__ agent_qs,
             float* __restrict__ q_out, float* __restrict__ w_out)
{
    const int b = blockIdx.x;
    const int tid = threadIdx.x;
    const int i = tid >> 4, c = tid & 15;

    __shared__ float w1s[W1N];
    __shared__ float ins[NAG][40];
    __shared__ float wfs[EDIM], b1s[EDIM];
    __shared__ float vtmp[EDIM];
    __shared__ float vredS;
    __shared__ float qpart[NAG];

    for (int idx = tid; idx < 640; idx += 256)
        ((float4*)w1s)[idx] = ((const float4*)(g_w1 + (size_t)b * W1N))[idx];
    for (int idx = tid; idx < 320; idx += 256) {
        ins[idx / NACT][idx % NACT]        = g_coal[b * 320 + idx];
        ins[idx / NACT][NACT + idx % NACT] = actions[b * 320 + idx];
    }
    if (tid < 64) {
        wfs[tid]  = g_wf[(size_t)b * EDIM + tid];
        b1s[tid]  = g_out0[(size_t)b * CATN + 512 + tid];
        vtmp[tid] = g_out0[(size_t)b * CATN + 576 + tid] * Wv2[tid];
    }
    __syncthreads();

    if (tid < 32) {
        float pv = vtmp[tid] + vtmp[tid + 32];
#pragma unroll
        for (int o = 16; o > 0; o >>= 1)
            pv += __shfl_down_sync(0xffffffffu, pv, o);
        if (tid == 0) vredS = pv + bv2[0];
    }
    __syncthreads();

    const int e0 = c * 4;
    float4 hb = *(const float4*)&b1s[e0];
    float h[4] = {hb.x, hb.y, hb.z, hb.w};
#pragma unroll
    for (int k = 0; k < 40; k++) {
        float a_ = ins[i][k];
        float4 w = *(const float4*)&w1s[k * EDIM + e0];
        h[0] += a_ * w.x; h[1] += a_ * w.y;
        h[2] += a_ * w.z; h[3] += a_ * w.w;
    }
    float4 wfv = *(const float4*)&wfs[e0];
    float pr = 0.f;
    {
        float hd0 = h[0] > 0.f ? h[0] : expm1f(h[0]);
        float hd1 = h[1] > 0.f ? h[1] : expm1f(h[1]);
        float hd2 = h[2] > 0.f ? h[2] : expm1f(h[2]);
        float hd3 = h[3] > 0.f ? h[3] : expm1f(h[3]);
        pr = hd0 * wfv.x + hd1 * wfv.y + hd2 * wfv.z + hd3 * wfv.w;
    }
#pragma unroll
    for (int o = 8; o > 0; o >>= 1)
        pr += __shfl_down_sync(0xffffffffu, pr, o, 16);
    if (c == 0) {
        float y = pr + vredS;
        float w = fabsf(y);
        if (w_out) w_out[b * NAG + i] = w;
        qpart[i] = w * agent_qs[b * NAG + i];
    }
    __syncthreads();
    if (tid == 0 && q_out) {
        float q = 0.f;
#pragma unroll
        for (int ii = 0; ii < NAG; ii++) q += qpart[ii];
        q_out[b] = q;
    }
}

// ======================================================================
// launch
// ======================================================================
extern "C" void kernel_launch(void* const* d_in, const int* in_sizes, int n_in,
                              void* d_out, int out_size)
{
    const float* states    = (const float*)d_in[0];
    const float* actions   = (const float*)d_in[1];
    const float* agent_qs  = (const float*)d_in[2];
    const int*   gc        = (const int*)  d_in[4];
    const float* W1a = (const float*)d_in[5];
    const float* b1a = (const float*)d_in[6];
    const float* W1b = (const float*)d_in[7];
    const float* b1b = (const float*)d_in[8];
    const float* Wb  = (const float*)d_in[9];
    const float* bb  = (const float*)d_in[10];
    const float* Wfa = (const float*)d_in[11];
    const float* bfa = (const float*)d_in[12];
    const float* Wfb = (const float*)d_in[13];
    const float* bfb = (const float*)d_in[14];
    const float* Wv1 = (const float*)d_in[15];
    const float* bv1 = (const float*)d_in[16];
    const float* Wv2 = (const float*)d_in[17];
    const float* bv2 = (const float*)d_in[18];

    static bool inited = false;
    if (!inited) {
        cudaFuncSetAttribute(stage2_kernel, cudaFuncAttributeMaxDynamicSharedMemorySize, SMEM_S2);
        inited = true;
    }

    float* out = (float*)d_out;
    float* q_out = nullptr;
    float* w_out = nullptr;
    if (out_size == BATCH + BATCH * NAG)      { q_out = out; w_out = out + BATCH; }
    else if (out_size == BATCH * NAG)         { w_out = out; }
    else if (out_size == BATCH)               { q_out = out; }
    else                                      { q_out = out; w_out = out + BATCH; }

    stage1_kernel<<<S1_TOTAL, 256>>>(states, W1a, b1a, Wfa, bfa, Wb, bb, Wv1, bv1,
                                     W1b, actions, gc);
    stage2_kernel<<<320 + 128, 256, SMEM_S2>>>(b1b, Wfb, bfb);
    final_kernel<<<BATCH, 256>>>(actions, Wv2, bv2, agent_qs, q_out, w_out);
}